// round 6
// baseline (speedup 1.0000x reference)
#include <cuda_runtime.h>
#include <cstdint>

// Problem constants (shapes fixed by the dataset)
#define HDIM 300
#define BM 128
#define BN 128      // 32 hidden units * 4 gates
#define BK 16
#define NTHREADS 256
#define SMS 20      // smem row stride (16 + 4 pad)
#define NKT 19      // ceil(300/16)
#define STATE_ELEMS (4096 * HDIM)

// State scratch (device globals: no allocation allowed).
// g_h0 is DOUBLE-BUFFERED: layer-0 reads h0[(t-1)&1] and writes h0[t&1].
// (In-place update raced across CTAs: every by-CTA reads all h columns while
// writer CTAs overwrite them — the 3.2e-3 error in R3/R4.)
__device__ float g_h0[2 * STATE_ELEMS];
__device__ float g_c0[STATE_ELEMS];
__device__ float g_c1[STATE_ELEMS];

__device__ __forceinline__ uint32_t f2tf32(float f) {
    uint32_t u;
    asm("cvt.rna.tf32.f32 %0, %1;" : "=r"(u) : "f"(f));
    return u;
}

// Split v = hi + lo (both tf32-representable); classic 3xTF32 decomposition.
__device__ __forceinline__ void tf32_split(float v, uint32_t& hi, uint32_t& lo) {
    hi = f2tf32(v);
    float r = v - __uint_as_float(hi);   // exact
    lo = f2tf32(r);
}

// One fused LSTM cell with 3xTF32 precision-compensated GEMMs:
// gates = x @ W_ih^T + hprev @ W_hh^T + (b_ih + b_hh); i,f,g,o; c/h update.
// Column mapping in the BN tile: n = 4*h_local + gate (weight row gate*300+h),
// so the epilogue assembles all 4 gates of one hidden unit with one shfl_xor(1).
__global__ __launch_bounds__(NTHREADS, 2) void lstm_cell_kernel(
    const float* __restrict__ x, int xStride,
    const float* __restrict__ hprev, int hStride,
    const float* __restrict__ cprev,
    const float* __restrict__ W_ih,
    const float* __restrict__ W_hh,
    const float* __restrict__ b_ih,
    const float* __restrict__ b_hh,
    float* __restrict__ hout, int hOutStride,
    float* __restrict__ cout)
{
    __shared__ uint32_t AsH[BM * SMS];
    __shared__ uint32_t AsL[BM * SMS];
    __shared__ uint32_t BsH[BN * SMS];
    __shared__ uint32_t BsL[BN * SMS];
    __shared__ float bias_s[128];  // [gate][32 h]

    const int tid   = threadIdx.x;
    const int lane  = tid & 31;
    const int warp  = tid >> 5;
    const int warpM = warp >> 2;   // 0..1  -> 64 rows each
    const int warpN = warp & 3;    // 0..3  -> 32 cols each (8 h * 4 gates)
    const int gId   = lane >> 2;
    const int tid4  = lane & 3;

    const int mBase = blockIdx.x * BM;
    const int hb    = blockIdx.y * 32;

    if (tid < 128) {
        int g = tid >> 5, hl = tid & 31, h = hb + hl;
        bias_s[tid] = (h < HDIM) ? (b_ih[g * HDIM + h] + b_hh[g * HDIM + h]) : 0.f;
    }

    float acc[4][4][4];
#pragma unroll
    for (int i = 0; i < 4; i++)
#pragma unroll
        for (int j = 0; j < 4; j++)
#pragma unroll
            for (int k = 0; k < 4; k++) acc[i][j][k] = 0.f;

#pragma unroll 1
    for (int seg = 0; seg < 2; seg++) {
        const float* src = seg ? hprev : x;
        const int sStride = seg ? hStride : xStride;
        const float* W = seg ? W_hh : W_ih;
        if (src == nullptr) continue;  // zero initial state: skip whole GEMM segment

#pragma unroll 1
        for (int kt = 0; kt < NKT; kt++) {
            const int k0 = kt * BK;
            // ---- stage A tile [BM x BK] hi/lo ----
#pragma unroll
            for (int i = 0; i < 2; i++) {
                int idx = tid + i * NTHREADS;      // 0..511 float4 slots
                int m = idx >> 2;                  // 4 float4 per 16-wide row
                int kv = (idx & 3) * 4;
                int k = k0 + kv;
                float4 v = make_float4(0.f, 0.f, 0.f, 0.f);
                if (k < HDIM)
                    v = *(const float4*)(src + (size_t)(mBase + m) * sStride + k);
                uint32_t* dh = &AsH[m * SMS + kv];
                uint32_t* dl = &AsL[m * SMS + kv];
                tf32_split(v.x, dh[0], dl[0]);
                tf32_split(v.y, dh[1], dl[1]);
                tf32_split(v.z, dh[2], dl[2]);
                tf32_split(v.w, dh[3], dl[3]);
            }
            // ---- stage B tile [BN x BK] hi/lo: row n -> W[gate*H + h, k] ----
#pragma unroll
            for (int i = 0; i < 2; i++) {
                int idx = tid + i * NTHREADS;
                int n = idx >> 2;
                int kv = (idx & 3) * 4;
                int k = k0 + kv;
                int gate = n & 3;
                int h = hb + (n >> 2);
                float4 v = make_float4(0.f, 0.f, 0.f, 0.f);
                if (k < HDIM && h < HDIM)
                    v = *(const float4*)(W + (size_t)(gate * HDIM + h) * HDIM + k);
                uint32_t* dh = &BsH[n * SMS + kv];
                uint32_t* dl = &BsL[n * SMS + kv];
                tf32_split(v.x, dh[0], dl[0]);
                tf32_split(v.y, dh[1], dl[1]);
                tf32_split(v.z, dh[2], dl[2]);
                tf32_split(v.w, dh[3], dl[3]);
            }
            __syncthreads();

#pragma unroll
            for (int kk = 0; kk < 2; kk++) {
                const int ko = kk * 8;
                uint32_t bH[4][2], bL[4][2];
#pragma unroll
                for (int ni = 0; ni < 4; ni++) {
                    int nb = warpN * 32 + ni * 8;
                    bH[ni][0] = BsH[(nb + gId) * SMS + ko + tid4];
                    bH[ni][1] = BsH[(nb + gId) * SMS + ko + tid4 + 4];
                    bL[ni][0] = BsL[(nb + gId) * SMS + ko + tid4];
                    bL[ni][1] = BsL[(nb + gId) * SMS + ko + tid4 + 4];
                }
#pragma unroll
                for (int mi = 0; mi < 4; mi++) {
                    int rb = warpM * 64 + mi * 16;
                    uint32_t aH[4], aL[4];
                    aH[0] = AsH[(rb + gId) * SMS + ko + tid4];
                    aH[1] = AsH[(rb + gId + 8) * SMS + ko + tid4];
                    aH[2] = AsH[(rb + gId) * SMS + ko + tid4 + 4];
                    aH[3] = AsH[(rb + gId + 8) * SMS + ko + tid4 + 4];
                    aL[0] = AsL[(rb + gId) * SMS + ko + tid4];
                    aL[1] = AsL[(rb + gId + 8) * SMS + ko + tid4];
                    aL[2] = AsL[(rb + gId) * SMS + ko + tid4 + 4];
                    aL[3] = AsL[(rb + gId + 8) * SMS + ko + tid4 + 4];
#pragma unroll
                    for (int ni = 0; ni < 4; ni++) {
                        // hi*lo cross terms first, then hi*hi
                        asm volatile(
                            "mma.sync.aligned.m16n8k8.row.col.f32.tf32.tf32.f32 "
                            "{%0,%1,%2,%3}, {%4,%5,%6,%7}, {%8,%9}, {%0,%1,%2,%3};\n"
                            : "+f"(acc[mi][ni][0]), "+f"(acc[mi][ni][1]),
                              "+f"(acc[mi][ni][2]), "+f"(acc[mi][ni][3])
                            : "r"(aH[0]), "r"(aH[1]), "r"(aH[2]), "r"(aH[3]),
                              "r"(bL[ni][0]), "r"(bL[ni][1]));
                        asm volatile(
                            "mma.sync.aligned.m16n8k8.row.col.f32.tf32.tf32.f32 "
                            "{%0,%1,%2,%3}, {%4,%5,%6,%7}, {%8,%9}, {%0,%1,%2,%3};\n"
                            : "+f"(acc[mi][ni][0]), "+f"(acc[mi][ni][1]),
                              "+f"(acc[mi][ni][2]), "+f"(acc[mi][ni][3])
                            : "r"(aL[0]), "r"(aL[1]), "r"(aL[2]), "r"(aL[3]),
                              "r"(bH[ni][0]), "r"(bH[ni][1]));
                        asm volatile(
                            "mma.sync.aligned.m16n8k8.row.col.f32.tf32.tf32.f32 "
                            "{%0,%1,%2,%3}, {%4,%5,%6,%7}, {%8,%9}, {%0,%1,%2,%3};\n"
                            : "+f"(acc[mi][ni][0]), "+f"(acc[mi][ni][1]),
                              "+f"(acc[mi][ni][2]), "+f"(acc[mi][ni][3])
                            : "r"(aH[0]), "r"(aH[1]), "r"(aH[2]), "r"(aH[3]),
                              "r"(bH[ni][0]), "r"(bH[ni][1]));
                    }
                }
            }
            __syncthreads();
        }
    }

    // ---- epilogue: assemble i,f,g,o per hidden unit via shfl_xor(1) ----
#pragma unroll
    for (int mi = 0; mi < 4; mi++) {
        const int row_r = mBase + warpM * 64 + mi * 16 + gId;
#pragma unroll
        for (int ni = 0; ni < 4; ni++) {
            float c0v = acc[mi][ni][0], c1v = acc[mi][ni][1];
            float c2v = acc[mi][ni][2], c3v = acc[mi][ni][3];
            float p0 = __shfl_xor_sync(0xffffffffu, c0v, 1);
            float p1 = __shfl_xor_sync(0xffffffffu, c1v, 1);
            float p2 = __shfl_xor_sync(0xffffffffu, c2v, 1);
            float p3 = __shfl_xor_sync(0xffffffffu, c3v, 1);

            const int hl = warpN * 8 + ni * 2 + (tid4 >> 1);
            const int h = hb + hl;
            float iraw, fraw, graw, oraw;
            int row;
            if ((tid4 & 1) == 0) {
                iraw = c0v; fraw = c1v; graw = p0; oraw = p1; row = row_r;
            } else {
                iraw = p2; fraw = p3; graw = c2v; oraw = c3v; row = row_r + 8;
            }
            if (h < HDIM) {
                iraw += bias_s[hl];
                fraw += bias_s[32 + hl];
                graw += bias_s[64 + hl];
                oraw += bias_s[96 + hl];
                float ig = 1.f / (1.f + expf(-iraw));
                float fg = 1.f / (1.f + expf(-fraw));
                float gg = tanhf(graw);
                float og = 1.f / (1.f + expf(-oraw));
                float cp = cprev ? cprev[(size_t)row * HDIM + h] : 0.f;
                float cn = fg * cp + ig * gg;
                float hn = og * tanhf(cn);
                cout[(size_t)row * HDIM + h] = cn;
                hout[(size_t)row * hOutStride + h] = hn;
            }
        }
    }
}

extern "C" void kernel_launch(void* const* d_in, const int* in_sizes, int n_in,
                              void* d_out, int out_size)
{
    const float* z     = (const float*)d_in[0];
    const float* W_ih0 = (const float*)d_in[1];
    const float* W_hh0 = (const float*)d_in[2];
    const float* b_ih0 = (const float*)d_in[3];
    const float* b_hh0 = (const float*)d_in[4];
    const float* W_ih1 = (const float*)d_in[5];
    const float* W_hh1 = (const float*)d_in[6];
    const float* b_ih1 = (const float*)d_in[7];
    const float* b_hh1 = (const float*)d_in[8];
    float* out = (float*)d_out;

    const int Bsz = in_sizes[0] / HDIM;      // 4096
    const int T   = out_size / (Bsz * HDIM); // 64

    float *h0base, *c0, *c1;
    cudaGetSymbolAddress((void**)&h0base, g_h0);
    cudaGetSymbolAddress((void**)&c0, g_c0);
    cudaGetSymbolAddress((void**)&c1, g_c1);

    dim3 grid(Bsz / BM, (HDIM + 31) / 32);   // 32 x 10
    dim3 block(NTHREADS);

    for (int t = 0; t < T; t++) {
        // ping-pong h0 buffers: read (t-1)&1, write t&1 (fixes inter-CTA race)
        float* h0_wr = h0base + (size_t)(t & 1) * STATE_ELEMS;
        float* h0_rd = h0base + (size_t)((t + 1) & 1) * STATE_ELEMS;

        // layer 0: input is z at t=0, else previous top-layer output (out slice)
        const float* x0  = (t == 0) ? z : out + (size_t)(t - 1) * HDIM;
        const int    x0s = (t == 0) ? HDIM : T * HDIM;
        const float* hp0 = (t == 0) ? nullptr : h0_rd;
        const float* cp0 = (t == 0) ? nullptr : c0;
        lstm_cell_kernel<<<grid, block>>>(x0, x0s, hp0, HDIM, cp0,
                                          W_ih0, W_hh0, b_ih0, b_hh0,
                                          h0_wr, HDIM, c0);

        // layer 1: input is h0 (just produced); recurrent h is out slice t-1;
        // writes h directly into the output slice for step t
        const float* hp1 = (t == 0) ? nullptr : out + (size_t)(t - 1) * HDIM;
        const float* cp1 = (t == 0) ? nullptr : c1;
        lstm_cell_kernel<<<grid, block>>>(h0_wr, HDIM, hp1, T * HDIM, cp1,
                                          W_ih1, W_hh1, b_ih1, b_hh1,
                                          out + (size_t)t * HDIM, T * HDIM, c1);
    }
}

// round 7
// speedup vs baseline: 1.8105x; 1.8105x over previous
#include <cuda_runtime.h>
#include <cuda_bf16.h>
#include <cstdint>

// ---- problem constants ----
#define HDIM 300
#define HPAD 320          // padded k extent (bf16 elems) for pair arrays
#define HPAIR 160         // uint32 (bf16x2) pairs per row
#define BROWS 4096
#define BM 128            // batch rows per CTA
#define BH 40             // hidden units per CTA  -> grid.y = 8, 256 CTAs = 1 wave
#define BNC 160           // gate-columns per CTA (4*BH)
#define KPAIR 16          // k-pairs per tile (BK=32)
#define SMS 20            // smem row stride in uint32 (16 + 4 pad)
#define NKT 10            // ceil(300/32), tail zero-padded
#define NTHREADS 256
#define NHB 8
#define NW 1280           // padded (row-permuted) weight rows (>= NHB*BH*4)
#define PAIRSZ (BROWS * HPAIR)

// ---- device scratch (no allocation allowed) ----
__device__ uint32_t g_zH[PAIRSZ], g_zL[PAIRSZ];
__device__ uint32_t g_h0H[2 * PAIRSZ], g_h0L[2 * PAIRSZ];   // ping-pong layer0 h
__device__ uint32_t g_oH[2 * PAIRSZ], g_oL[2 * PAIRSZ];     // ping-pong layer1 h (pairs)
__device__ uint32_t g_WH[4 * NW * HPAIR], g_WL[4 * NW * HPAIR]; // Wih0,Whh0,Wih1,Whh1
__device__ float g_c0[BROWS * HDIM], g_c1[BROWS * HDIM];

__device__ __forceinline__ uint32_t pack2(__nv_bfloat16 a, __nv_bfloat16 b) {
    return (uint32_t)__bfloat16_as_ushort(a) | ((uint32_t)__bfloat16_as_ushort(b) << 16);
}
// Compensated split: v = hi + lo (both bf16); dropped lo*lo term ~2^-18 relative.
__device__ __forceinline__ void split_pack(float v0, float v1, uint32_t& hi, uint32_t& lo) {
    __nv_bfloat16 h0 = __float2bfloat16(v0);
    __nv_bfloat16 h1 = __float2bfloat16(v1);
    float r0 = v0 - __bfloat162float(h0);   // exact
    float r1 = v1 - __bfloat162float(h1);
    hi = pack2(h0, h1);
    lo = pack2(__float2bfloat16(r0), __float2bfloat16(r1));
}

// Pre-split weights into row-permuted (n = 4*h + gate), zero-padded bf16 hi/lo pairs.
__global__ void prep_weights(const float* __restrict__ W0, const float* __restrict__ W1,
                             const float* __restrict__ W2, const float* __restrict__ W3) {
    int idx = blockIdx.x * blockDim.x + threadIdx.x;
    if (idx >= 4 * NW * HPAIR) return;
    int mat = idx / (NW * HPAIR);
    int rem = idx - mat * (NW * HPAIR);
    int n = rem / HPAIR;
    int p = rem - n * HPAIR;
    const float* W = (mat == 0) ? W0 : (mat == 1) ? W1 : (mat == 2) ? W2 : W3;
    int gate = n & 3, h = n >> 2;
    int k = p * 2;
    float v0 = 0.f, v1 = 0.f;
    if (h < HDIM) {
        const float* row = W + (size_t)(gate * HDIM + h) * HDIM;
        if (k < HDIM)     v0 = row[k];
        if (k + 1 < HDIM) v1 = row[k + 1];
    }
    uint32_t hi, lo;
    split_pack(v0, v1, hi, lo);
    g_WH[idx] = hi;
    g_WL[idx] = lo;
}

// Pre-split z into bf16 hi/lo pair array [4096][HPAIR].
__global__ void prep_z(const float* __restrict__ z) {
    int idx = blockIdx.x * blockDim.x + threadIdx.x;
    if (idx >= PAIRSZ) return;
    int r = idx / HPAIR;
    int p = idx - r * HPAIR;
    int k = p * 2;
    float v0 = (k < HDIM) ? z[(size_t)r * HDIM + k] : 0.f;
    float v1 = (k + 1 < HDIM) ? z[(size_t)r * HDIM + k + 1] : 0.f;
    uint32_t hi, lo;
    split_pack(v0, v1, hi, lo);
    g_zH[idx] = hi;
    g_zL[idx] = lo;
}

// Fused LSTM cell, bf16x2-compensated (3 bf16 m16n8k16 MMAs per 16-k slab):
// gates = x @ Wx^T + hprev @ Wh^T + bias; i,f,g,o; c/h update.
// All A/B operands arrive pre-split as bf16 pairs -> staging is pure copy.
__global__ __launch_bounds__(NTHREADS, 2) void lstm_cell(
    const uint32_t* __restrict__ xH, const uint32_t* __restrict__ xL,
    const uint32_t* __restrict__ hH, const uint32_t* __restrict__ hL,   // null at t=0
    const float* __restrict__ cprev,                                     // null at t=0
    const uint32_t* __restrict__ WxH, const uint32_t* __restrict__ WxL,
    const uint32_t* __restrict__ WhH, const uint32_t* __restrict__ WhL,
    const float* __restrict__ b_ih, const float* __restrict__ b_hh,
    uint32_t* __restrict__ hpH, uint32_t* __restrict__ hpL,              // bf16-pair h out
    float* __restrict__ houtF, int hOutStride,                           // optional fp32 h out
    float* __restrict__ cout)
{
    __shared__ __align__(16) uint32_t AsH[BM * SMS];
    __shared__ __align__(16) uint32_t AsL[BM * SMS];
    __shared__ __align__(16) uint32_t BsH[BNC * SMS];
    __shared__ __align__(16) uint32_t BsL[BNC * SMS];
    __shared__ float bias_s[BNC];   // [4*hl + gate]

    const int tid   = threadIdx.x;
    const int lane  = tid & 31;
    const int warp  = tid >> 5;
    const int warpM = warp >> 2;    // 0..1 -> 64 rows each
    const int warpN = warp & 3;     // 0..3 -> 40 cols each (10 h * 4 gates)
    const int gId   = lane >> 2;
    const int tid4  = lane & 3;

    const int mBase = blockIdx.x * BM;
    const int hb    = blockIdx.y * BH;
    const int nBase = hb * 4;       // first permuted weight row for this CTA

    if (tid < BNC) {
        int gate = tid & 3, hl = tid >> 2, h = hb + hl;
        bias_s[tid] = (h < HDIM) ? (b_ih[gate * HDIM + h] + b_hh[gate * HDIM + h]) : 0.f;
    }

    float acc[4][5][4];
#pragma unroll
    for (int a = 0; a < 4; a++)
#pragma unroll
        for (int b = 0; b < 5; b++)
#pragma unroll
            for (int c = 0; c < 4; c++) acc[a][b][c] = 0.f;

#pragma unroll 1
    for (int seg = 0; seg < 2; seg++) {
        const uint32_t* aHsrc = seg ? hH : xH;
        const uint32_t* aLsrc = seg ? hL : xL;
        const uint32_t* bHsrc = seg ? WhH : WxH;
        const uint32_t* bLsrc = seg ? WhL : WxL;
        if (aHsrc == nullptr) continue;   // zero initial state

#pragma unroll 1
        for (int kt = 0; kt < NKT; kt++) {
            const int p0 = kt * KPAIR;
            // ---- stage A tiles (hi then lo), pure uint4 copy; pad rows are zero ----
#pragma unroll
            for (int i2 = 0; i2 < 4; i2++) {
                int s = tid + i2 * NTHREADS;              // 0..1023
                int r = (s >> 2) & (BM - 1);
                int q = s & 3;
                const uint32_t* src = (s < 512) ? aHsrc : aLsrc;
                uint32_t* dst = (s < 512) ? AsH : AsL;
                uint4 v = *(const uint4*)(src + (size_t)(mBase + r) * HPAIR + p0 + q * 4);
                *(uint4*)(dst + r * SMS + q * 4) = v;
            }
            // ---- stage B tiles (contiguous permuted weight rows) ----
#pragma unroll
            for (int i2 = 0; i2 < 5; i2++) {
                int s = tid + i2 * NTHREADS;              // 0..1279
                int sp = (s >= 640);
                int ss = sp ? s - 640 : s;
                int r = ss >> 2;
                int q = ss & 3;
                const uint32_t* src = sp ? bLsrc : bHsrc;
                uint32_t* dst = sp ? BsL : BsH;
                uint4 v = *(const uint4*)(src + (size_t)(nBase + r) * HPAIR + p0 + q * 4);
                *(uint4*)(dst + r * SMS + q * 4) = v;
            }
            __syncthreads();

#pragma unroll
            for (int kk = 0; kk < 2; kk++) {
                const int ko2 = kk * 8;                   // pair offset of this 16-k slab
                uint32_t bH[5][2], bL[5][2];
#pragma unroll
                for (int ni = 0; ni < 5; ni++) {
                    int nb = warpN * 40 + ni * 8;
                    bH[ni][0] = BsH[(nb + gId) * SMS + ko2 + tid4];
                    bH[ni][1] = BsH[(nb + gId) * SMS + ko2 + tid4 + 4];
                    bL[ni][0] = BsL[(nb + gId) * SMS + ko2 + tid4];
                    bL[ni][1] = BsL[(nb + gId) * SMS + ko2 + tid4 + 4];
                }
#pragma unroll
                for (int mi = 0; mi < 4; mi++) {
                    int rb = warpM * 64 + mi * 16;
                    uint32_t aH[4], aL[4];
                    aH[0] = AsH[(rb + gId) * SMS + ko2 + tid4];
                    aH[1] = AsH[(rb + gId + 8) * SMS + ko2 + tid4];
                    aH[2] = AsH[(rb + gId) * SMS + ko2 + tid4 + 4];
                    aH[3] = AsH[(rb + gId + 8) * SMS + ko2 + tid4 + 4];
                    aL[0] = AsL[(rb + gId) * SMS + ko2 + tid4];
                    aL[1] = AsL[(rb + gId + 8) * SMS + ko2 + tid4];
                    aL[2] = AsL[(rb + gId) * SMS + ko2 + tid4 + 4];
                    aL[3] = AsL[(rb + gId + 8) * SMS + ko2 + tid4 + 4];
#pragma unroll
                    for (int ni = 0; ni < 5; ni++) {
                        asm volatile(
                            "mma.sync.aligned.m16n8k16.row.col.f32.bf16.bf16.f32 "
                            "{%0,%1,%2,%3}, {%4,%5,%6,%7}, {%8,%9}, {%0,%1,%2,%3};\n"
                            : "+f"(acc[mi][ni][0]), "+f"(acc[mi][ni][1]),
                              "+f"(acc[mi][ni][2]), "+f"(acc[mi][ni][3])
                            : "r"(aH[0]), "r"(aH[1]), "r"(aH[2]), "r"(aH[3]),
                              "r"(bL[ni][0]), "r"(bL[ni][1]));
                        asm volatile(
                            "mma.sync.aligned.m16n8k16.row.col.f32.bf16.bf16.f32 "
                            "{%0,%1,%2,%3}, {%4,%5,%6,%7}, {%8,%9}, {%0,%1,%2,%3};\n"
                            : "+f"(acc[mi][ni][0]), "+f"(acc[mi][ni][1]),
                              "+f"(acc[mi][ni][2]), "+f"(acc[mi][ni][3])
                            : "r"(aL[0]), "r"(aL[1]), "r"(aL[2]), "r"(aL[3]),
                              "r"(bH[ni][0]), "r"(bH[ni][1]));
                        asm volatile(
                            "mma.sync.aligned.m16n8k16.row.col.f32.bf16.bf16.f32 "
                            "{%0,%1,%2,%3}, {%4,%5,%6,%7}, {%8,%9}, {%0,%1,%2,%3};\n"
                            : "+f"(acc[mi][ni][0]), "+f"(acc[mi][ni][1]),
                              "+f"(acc[mi][ni][2]), "+f"(acc[mi][ni][3])
                            : "r"(aH[0]), "r"(aH[1]), "r"(aH[2]), "r"(aH[3]),
                              "r"(bH[ni][0]), "r"(bH[ni][1]));
                    }
                }
            }
            __syncthreads();
        }
    }

    // ---- epilogue: assemble i,f,g,o per hidden unit via shfl_xor(1) ----
    __nv_bfloat16* hpH16 = (__nv_bfloat16*)hpH;
    __nv_bfloat16* hpL16 = (__nv_bfloat16*)hpL;
#pragma unroll
    for (int mi = 0; mi < 4; mi++) {
        const int row_r = mBase + warpM * 64 + mi * 16 + gId;
#pragma unroll
        for (int ni = 0; ni < 5; ni++) {
            float c0v = acc[mi][ni][0], c1v = acc[mi][ni][1];
            float c2v = acc[mi][ni][2], c3v = acc[mi][ni][3];
            float p0 = __shfl_xor_sync(0xffffffffu, c0v, 1);
            float p1 = __shfl_xor_sync(0xffffffffu, c1v, 1);
            float p2 = __shfl_xor_sync(0xffffffffu, c2v, 1);
            float p3 = __shfl_xor_sync(0xffffffffu, c3v, 1);

            const int hl = warpN * 10 + ni * 2 + (tid4 >> 1);
            const int h = hb + hl;
            float iraw, fraw, graw, oraw;
            int row;
            if ((tid4 & 1) == 0) {
                iraw = c0v; fraw = c1v; graw = p0; oraw = p1; row = row_r;
            } else {
                iraw = p2; fraw = p3; graw = c2v; oraw = c3v; row = row_r + 8;
            }
            if (h < HDIM) {
                iraw += bias_s[4 * hl + 0];
                fraw += bias_s[4 * hl + 1];
                graw += bias_s[4 * hl + 2];
                oraw += bias_s[4 * hl + 3];
                float ig = 1.f / (1.f + expf(-iraw));
                float fg = 1.f / (1.f + expf(-fraw));
                float gg = tanhf(graw);
                float og = 1.f / (1.f + expf(-oraw));
                float cp = cprev ? cprev[(size_t)row * HDIM + h] : 0.f;
                float cn = fg * cp + ig * gg;
                float hn = og * tanhf(cn);
                cout[(size_t)row * HDIM + h] = cn;
                // store h as compensated bf16 pair for downstream GEMMs
                __nv_bfloat16 hh = __float2bfloat16(hn);
                float rem = hn - __bfloat162float(hh);
                hpH16[(size_t)row * HPAD + h] = hh;
                hpL16[(size_t)row * HPAD + h] = __float2bfloat16(rem);
                if (houtF) houtF[(size_t)row * hOutStride + h] = hn;
            }
        }
    }
}

extern "C" void kernel_launch(void* const* d_in, const int* in_sizes, int n_in,
                              void* d_out, int out_size)
{
    const float* z     = (const float*)d_in[0];
    const float* W_ih0 = (const float*)d_in[1];
    const float* W_hh0 = (const float*)d_in[2];
    const float* b_ih0 = (const float*)d_in[3];
    const float* b_hh0 = (const float*)d_in[4];
    const float* W_ih1 = (const float*)d_in[5];
    const float* W_hh1 = (const float*)d_in[6];
    const float* b_ih1 = (const float*)d_in[7];
    const float* b_hh1 = (const float*)d_in[8];
    float* out = (float*)d_out;

    const int Bsz = in_sizes[0] / HDIM;      // 4096
    const int T   = out_size / (Bsz * HDIM); // 64

    uint32_t *zH, *zL, *h0H, *h0L, *oH, *oL, *WH, *WL;
    float *c0, *c1;
    cudaGetSymbolAddress((void**)&zH, g_zH);
    cudaGetSymbolAddress((void**)&zL, g_zL);
    cudaGetSymbolAddress((void**)&h0H, g_h0H);
    cudaGetSymbolAddress((void**)&h0L, g_h0L);
    cudaGetSymbolAddress((void**)&oH, g_oH);
    cudaGetSymbolAddress((void**)&oL, g_oL);
    cudaGetSymbolAddress((void**)&WH, g_WH);
    cudaGetSymbolAddress((void**)&WL, g_WL);
    cudaGetSymbolAddress((void**)&c0, g_c0);
    cudaGetSymbolAddress((void**)&c1, g_c1);

    const int WSTEP = NW * HPAIR;

    // one-time (per call) operand pre-splitting
    prep_weights<<<(4 * WSTEP + 255) / 256, 256>>>(W_ih0, W_hh0, W_ih1, W_hh1);
    prep_z<<<(PAIRSZ + 255) / 256, 256>>>(z);

    dim3 grid(Bsz / BM, NHB);   // 32 x 8 = 256 CTAs = one full wave
    dim3 block(NTHREADS);

    for (int t = 0; t < T; t++) {
        const int wr = t & 1, rd = (t + 1) & 1;

        // layer 0: x = z (t=0) else previous top output pairs; recurrent = h0 pairs
        const uint32_t* x0H = (t == 0) ? zH : oH + (size_t)rd * PAIRSZ;
        const uint32_t* x0L = (t == 0) ? zL : oL + (size_t)rd * PAIRSZ;
        const uint32_t* hp0H = (t == 0) ? nullptr : h0H + (size_t)rd * PAIRSZ;
        const uint32_t* hp0L = (t == 0) ? nullptr : h0L + (size_t)rd * PAIRSZ;
        const float* cp0 = (t == 0) ? nullptr : c0;
        lstm_cell<<<grid, block>>>(x0H, x0L, hp0H, hp0L, cp0,
                                   WH + 0 * WSTEP, WL + 0 * WSTEP,
                                   WH + 1 * WSTEP, WL + 1 * WSTEP,
                                   b_ih0, b_hh0,
                                   h0H + (size_t)wr * PAIRSZ, h0L + (size_t)wr * PAIRSZ,
                                   nullptr, 0, c0);

        // layer 1: x = h0 pairs (just produced); recurrent = out pairs (t-1);
        // also writes fp32 h into the final output slice for step t
        const uint32_t* hp1H = (t == 0) ? nullptr : oH + (size_t)rd * PAIRSZ;
        const uint32_t* hp1L = (t == 0) ? nullptr : oL + (size_t)rd * PAIRSZ;
        const float* cp1 = (t == 0) ? nullptr : c1;
        lstm_cell<<<grid, block>>>(h0H + (size_t)wr * PAIRSZ, h0L + (size_t)wr * PAIRSZ,
                                   hp1H, hp1L, cp1,
                                   WH + 2 * WSTEP, WL + 2 * WSTEP,
                                   WH + 3 * WSTEP, WL + 3 * WSTEP,
                                   b_ih1, b_hh1,
                                   oH + (size_t)wr * PAIRSZ, oL + (size_t)wr * PAIRSZ,
                                   out + (size_t)t * HDIM, T * HDIM, c1);
    }
}